// round 16
// baseline (speedup 1.0000x reference)
#include <cuda_runtime.h>
#include <cuda_fp16.h>
#include <cstdint>
#include <math.h>

#define NUM_USERS 8192
#define NUM_ITEMS 32768
#define FEAT      129
#define BM        128
#define BN        128
#define NTILES_N  256               // 32768 / 128
#define NTILES    16384             // 64 * 256
#define NTHREADS  256               // 8 warps, each 64x32

// ---- scratch (__device__ globals: allocation-free) ----
// A (users): per row 256 halfs = [xh 0..127 | xl 128..255], x ~= xh + xl (fp16 pair)
// B (items): per row 128 halfs = yh (fp16), sign fold on k=0
__device__ __align__(256) __half g_A16[(size_t)NUM_USERS * 256];
__device__ __align__(256) __half g_B16[(size_t)NUM_ITEMS * 128];
__device__ __align__(16) float g_A129[NUM_USERS];   // feature 128, exact fp32 (rank-1 peel)
__device__ __align__(16) float g_B129[NUM_ITEMS];

__device__ __forceinline__ uint32_t smem_u32(const void* p) {
    uint32_t a;
    asm("{ .reg .u64 t; cvta.to.shared.u64 t, %1; cvt.u32.u64 %0, t; }" : "=r"(a) : "l"(p));
    return a;
}
#define SW128(off) ((off) ^ (((off) >> 3) & 0x70))
#define CPA(dst, src) asm volatile("cp.async.cg.shared.global [%0], [%1], 16;" :: "r"(dst), "l"(src))

// ---- prep: sign fold, users -> (hi, lo) fp16, items -> fp16, rank-1 vectors ----
__global__ void prep_kernel(const float* __restrict__ h) {
    int idx = blockIdx.x * blockDim.x + threadIdx.x;
    const int totA = NUM_USERS * 128;
    const int totB = NUM_ITEMS * 128;
    if (idx < totA) {
        int u = idx >> 7, k = idx & 127;
        float x = h[(size_t)u * FEAT + k];
        __half xh = __float2half_rn(x);
        __half xl = __float2half_rn(x - __half2float(xh));
        g_A16[(size_t)u * 256 + k]       = xh;
        g_A16[(size_t)u * 256 + 128 + k] = xl;
    } else if (idx < totA + totB) {
        int j = idx - totA;
        int i = j >> 7, k = j & 127;
        float y = h[(size_t)(NUM_USERS + i) * FEAT + k];
        if (k == 0) y = -y;   // signs[0] = -1 folded into items
        g_B16[(size_t)i * 128 + k] = __float2half_rn(y);
    } else if (idx < totA + totB + NUM_USERS) {
        int u = idx - totA - totB;
        g_A129[u] = h[(size_t)u * FEAT + 128];
    } else if (idx < totA + totB + NUM_USERS + NUM_ITEMS) {
        int i = idx - totA - totB - NUM_USERS;
        g_B129[i] = h[(size_t)(NUM_USERS + i) * FEAT + 128];
    }
}

// per-stage layout (16KB blocks, SW128 rows of 128B): Ah[2 chunks]|Al[2]|B[2]|a129|b129
#define OFF_AH   0
#define OFF_AL   32768
#define OFF_B    65536
#define OFF_A129 98304
#define OFF_B129 98816
#define STAGE    99328
#define SM_SIZE  (2 * STAGE)        // 198656

__global__ __launch_bounds__(NTHREADS, 1)
void gemm_f16_persistent(float* __restrict__ out) {
    extern __shared__ __align__(1024) char smem[];
    const uint32_t sb = smem_u32(smem);
    const int tid = threadIdx.x;
    const int wid = tid >> 5;
    const int L = tid & 31;
    const int mb = (wid & 1) * 64;    // 2 warps in m
    const int nb = (wid >> 1) * 32;   // 4 warps in n

    // per-lane ldmatrix addressing (SW128 swizzle: XOR = (row&7)*16)
    const uint32_t xorv = (L & 7) * 16;
    const uint32_t kha = (L >> 4) * 16;
    const uint32_t khb = ((L >> 3) & 1) * 16;
    uint32_t aBase[4], bBase[2];
    #pragma unroll
    for (int mi = 0; mi < 4; mi++)
        aBase[mi] = (uint32_t)(mb + mi * 16 + (L & 7) + ((L >> 3) & 1) * 8) * 128;
    #pragma unroll
    for (int p = 0; p < 2; p++)
        bBase[p] = (uint32_t)(nb + p * 16 + (L & 7) + ((L >> 4) & 1) * 8) * 128;

    // cooperative tile load: 97KB via cp.async (24-25 per thread), one commit group
    auto load_tile = [&](int t, int stg) {
        const uint32_t base = sb + stg * STAGE;
        const int m0 = (t >> 8) * BM, n0 = (t & (NTILES_N - 1)) * BN;
        const __half* srcA = g_A16 + (size_t)m0 * 256;
        const __half* srcB = g_B16 + (size_t)n0 * 128;
        #pragma unroll
        for (int c = 0; c < 2; c++) {
            #pragma unroll
            for (int it = 0; it < 4; it++) {   // 1024 lines x 16B per matrix-chunk
                int idx = tid + it * NTHREADS; int row = idx >> 3, sg = idx & 7;
                uint32_t off = SW128((uint32_t)(row * 128 + sg * 16));
                CPA(base + OFF_AH + c * 16384 + off, srcA + row * 256 + c * 64 + sg * 8);
                CPA(base + OFF_AL + c * 16384 + off, srcA + row * 256 + 128 + c * 64 + sg * 8);
                CPA(base + OFF_B  + c * 16384 + off, srcB + row * 128 + c * 64 + sg * 8);
            }
        }
        if (tid < 32)       CPA(base + OFF_A129 + tid * 16, g_A129 + m0 + tid * 4);
        else if (tid < 64)  CPA(base + OFF_B129 + (tid - 32) * 16, g_B129 + n0 + (tid - 32) * 4);
        asm volatile("cp.async.commit_group;" ::: "memory");
    };

    float acc[2][4][4][4];            // two 64-reg banks (tile-parity ping-pong)
    float sA[2][8], sB[2][8];         // rank-1 scalars latched per bank

    auto load_scalars = [&](int stg) {
        const uint32_t base = sb + stg * STAGE;
        #pragma unroll
        for (int mi = 0; mi < 4; mi++) {
            int rr = mb + mi * 16 + (L >> 2);
            asm volatile("ld.shared.f32 %0, [%1];" : "=f"(sA[stg][mi*2])   : "r"(base + OFF_A129 + rr * 4));
            asm volatile("ld.shared.f32 %0, [%1];" : "=f"(sA[stg][mi*2+1]) : "r"(base + OFF_A129 + (rr + 8) * 4));
        }
        #pragma unroll
        for (int ni = 0; ni < 4; ni++) {
            int cc = nb + ni * 8 + (L & 3) * 2;
            asm volatile("ld.shared.f32 %0, [%1];" : "=f"(sB[stg][ni*2])   : "r"(base + OFF_B129 + cc * 4));
            asm volatile("ld.shared.f32 %0, [%1];" : "=f"(sB[stg][ni*2+1]) : "r"(base + OFF_B129 + (cc + 1) * 4));
        }
    };

    // one k16-step: 2 B-ldsm + 4 Ah-ldsm + 4 Al-ldsm + 32 HMMA into bank stg
    auto mma_step = [&](int stg, int c, int ks) {
        const uint32_t base = sb + stg * STAGE;
        const uint32_t kofs = (uint32_t)ks * 32;
        uint32_t b[4][2];
        #pragma unroll
        for (int p = 0; p < 2; p++) {
            uint32_t addr = base + OFF_B + c * 16384 + bBase[p] + ((kofs + khb) ^ xorv);
            asm volatile("ldmatrix.sync.aligned.m8n8.x4.shared.b16 {%0,%1,%2,%3}, [%4];"
                : "=r"(b[2*p][0]), "=r"(b[2*p][1]), "=r"(b[2*p+1][0]), "=r"(b[2*p+1][1])
                : "r"(addr));
        }
        uint32_t ah[4][4], al[4][4];
        #pragma unroll
        for (int mi = 0; mi < 4; mi++) {
            uint32_t addr = base + OFF_AH + c * 16384 + aBase[mi] + ((kofs + kha) ^ xorv);
            asm volatile("ldmatrix.sync.aligned.m8n8.x4.shared.b16 {%0,%1,%2,%3}, [%4];"
                : "=r"(ah[mi][0]), "=r"(ah[mi][1]), "=r"(ah[mi][2]), "=r"(ah[mi][3]) : "r"(addr));
        }
        #pragma unroll
        for (int mi = 0; mi < 4; mi++) {
            uint32_t addr = base + OFF_AL + c * 16384 + aBase[mi] + ((kofs + kha) ^ xorv);
            asm volatile("ldmatrix.sync.aligned.m8n8.x4.shared.b16 {%0,%1,%2,%3}, [%4];"
                : "=r"(al[mi][0]), "=r"(al[mi][1]), "=r"(al[mi][2]), "=r"(al[mi][3]) : "r"(addr));
        }
        #pragma unroll
        for (int mi = 0; mi < 4; mi++)
            #pragma unroll
            for (int ni = 0; ni < 4; ni++) {
                asm volatile(
                    "mma.sync.aligned.m16n8k16.row.col.f32.f16.f16.f32 "
                    "{%0,%1,%2,%3}, {%4,%5,%6,%7}, {%8,%9}, {%0,%1,%2,%3};"
                    : "+f"(acc[stg][mi][ni][0]), "+f"(acc[stg][mi][ni][1]),
                      "+f"(acc[stg][mi][ni][2]), "+f"(acc[stg][mi][ni][3])
                    : "r"(ah[mi][0]), "r"(ah[mi][1]), "r"(ah[mi][2]), "r"(ah[mi][3]),
                      "r"(b[ni][0]), "r"(b[ni][1]));
            }
        #pragma unroll
        for (int mi = 0; mi < 4; mi++)
            #pragma unroll
            for (int ni = 0; ni < 4; ni++) {
                asm volatile(
                    "mma.sync.aligned.m16n8k16.row.col.f32.f16.f16.f32 "
                    "{%0,%1,%2,%3}, {%4,%5,%6,%7}, {%8,%9}, {%0,%1,%2,%3};"
                    : "+f"(acc[stg][mi][ni][0]), "+f"(acc[stg][mi][ni][1]),
                      "+f"(acc[stg][mi][ni][2]), "+f"(acc[stg][mi][ni][3])
                    : "r"(al[mi][0]), "r"(al[mi][1]), "r"(al[mi][2]), "r"(al[mi][3]),
                      "r"(b[ni][0]), "r"(b[ni][1]));
            }
    };

    // epilogue group g (mi = g>>2, ni = g&3): 4 outputs of the previous tile
    const float THMIN = 1.00000011920928955f;   // fp32(1 + 1e-7), identical to jnp
    const float NEGLN2SQ = -0.480453013918201f; // -(ln2)^2
    auto epi_group = [&](int pb, int pm0, int pn0, int g) {
        const int mi = g >> 2, ni = g & 3;
        const int rr = mb + mi * 16 + (L >> 2);
        const int r0 = pm0 + rr;
        const int col = pn0 + nb + ni * 8 + (L & 3) * 2;
        const float aam[4] = {sA[pb][mi*2], sA[pb][mi*2], sA[pb][mi*2+1], sA[pb][mi*2+1]};
        float v[4];
        #pragma unroll
        for (int r = 0; r < 4; r++) {
            float th = fmaxf(fmaf(-aam[r], sB[pb][ni*2 + (r & 1)], -acc[pb][mi][ni][r]), THMIN);
            float x = fmaf(th, th, -1.0f);
            float sq; asm("sqrt.approx.f32 %0, %1;" : "=f"(sq) : "f"(x));
            float lg; asm("lg2.approx.f32 %0, %1;" : "=f"(lg) : "f"(th + sq));
            v[r] = fmaxf(lg * lg * NEGLN2SQ, -50.0f);
        }
        *(float2*)(out + (size_t)r0 * NUM_ITEMS + col)       = make_float2(v[0], v[1]);
        *(float2*)(out + (size_t)(r0 + 8) * NUM_ITEMS + col) = make_float2(v[2], v[3]);
    };

    // ---- persistent mainloop with cross-tile pipelining ----
    load_tile(blockIdx.x, 0);
    int k = 0, pm0 = 0, pn0 = 0;
    for (int t = blockIdx.x; t < NTILES; t += gridDim.x, k++) {
        const int stg = k & 1;
        asm volatile("cp.async.wait_group 0;" ::: "memory");
        __syncthreads();          // load(t) visible; all warps done with stage stg (tile t-2)
        load_scalars(stg);
        const int tn = t + gridDim.x;
        if (tn < NTILES) load_tile(tn, stg ^ 1);
        #pragma unroll
        for (int mi = 0; mi < 4; mi++)
            #pragma unroll
            for (int ni = 0; ni < 4; ni++)
                #pragma unroll
                for (int r = 0; r < 4; r++) acc[stg][mi][ni][r] = 0.0f;
        const int pb = stg ^ 1;
        if (k > 0) {
            #pragma unroll
            for (int s = 0; s < 8; s++) {
                mma_step(stg, s >> 2, s & 3);
                epi_group(pb, pm0, pn0, 2 * s);
                epi_group(pb, pm0, pn0, 2 * s + 1);
            }
        } else {
            #pragma unroll
            for (int s = 0; s < 8; s++) mma_step(stg, s >> 2, s & 3);
        }
        pm0 = (t >> 8) * BM;
        pn0 = (t & (NTILES_N - 1)) * BN;
    }
    // tail: epilogue of the final tile (once per kernel)
    const int pb = (k - 1) & 1;
    #pragma unroll
    for (int g = 0; g < 16; g++) epi_group(pb, pm0, pn0, g);
}

extern "C" void kernel_launch(void* const* d_in, const int* in_sizes, int n_in,
                              void* d_out, int out_size) {
    const float* h = (const float*)d_in[0];
    float* out = (float*)d_out;

    const int totPrep = (NUM_USERS + NUM_ITEMS) * 128 + NUM_USERS + NUM_ITEMS;
    prep_kernel<<<(totPrep + 255) / 256, 256>>>(h);

    int nsm = 148;
    cudaDeviceGetAttribute(&nsm, cudaDevAttrMultiProcessorCount, 0);
    cudaFuncSetAttribute(gemm_f16_persistent, cudaFuncAttributeMaxDynamicSharedMemorySize, SM_SIZE);
    gemm_f16_persistent<<<nsm, NTHREADS, SM_SIZE>>>(out);
}

// round 17
// speedup vs baseline: 3.4691x; 3.4691x over previous
#include <cuda_runtime.h>
#include <cuda_fp16.h>
#include <cstdint>
#include <math.h>

#define NUM_USERS 8192
#define NUM_ITEMS 32768
#define FEAT      129
#define BM        128
#define BN        128
#define NTILES_N  256               // 32768 / 128
#define NTILES    16384             // 64 * 256
#define NTHREADS  256               // 8 warps, each 64x32

// ---- scratch (__device__ globals: allocation-free) ----
__device__ __align__(256) __half g_A16[(size_t)NUM_USERS * 256];  // [xh|xl] per row
__device__ __align__(256) __half g_B16[(size_t)NUM_ITEMS * 128];  // yh, sign-folded
__device__ __align__(16) float g_A129[NUM_USERS];
__device__ __align__(16) float g_B129[NUM_ITEMS];

__device__ __forceinline__ uint32_t smem_u32(const void* p) {
    uint32_t a;
    asm("{ .reg .u64 t; cvta.to.shared.u64 t, %1; cvt.u32.u64 %0, t; }" : "=r"(a) : "l"(p));
    return a;
}
#define SW128(off) ((off) ^ (((off) >> 3) & 0x70))
#define CPA(dst, src) asm volatile("cp.async.cg.shared.global [%0], [%1], 16;" :: "r"(dst), "l"(src))

__global__ void prep_kernel(const float* __restrict__ h) {
    int idx = blockIdx.x * blockDim.x + threadIdx.x;
    const int totA = NUM_USERS * 128;
    const int totB = NUM_ITEMS * 128;
    if (idx < totA) {
        int u = idx >> 7, k = idx & 127;
        float x = h[(size_t)u * FEAT + k];
        __half xh = __float2half_rn(x);
        __half xl = __float2half_rn(x - __half2float(xh));
        g_A16[(size_t)u * 256 + k]       = xh;
        g_A16[(size_t)u * 256 + 128 + k] = xl;
    } else if (idx < totA + totB) {
        int j = idx - totA;
        int i = j >> 7, k = j & 127;
        float y = h[(size_t)(NUM_USERS + i) * FEAT + k];
        if (k == 0) y = -y;
        g_B16[(size_t)i * 128 + k] = __float2half_rn(y);
    } else if (idx < totA + totB + NUM_USERS) {
        int u = idx - totA - totB;
        g_A129[u] = h[(size_t)u * FEAT + 128];
    } else if (idx < totA + totB + NUM_USERS + NUM_ITEMS) {
        int i = idx - totA - totB - NUM_USERS;
        g_B129[i] = h[(size_t)(NUM_USERS + i) * FEAT + 128];
    }
}

// per-stage layout: Ah[32K]|Al[32K]|B[32K]|a129[512B]|b129[512B] = 99328; 2 stages
#define OFF_AH   0
#define OFF_AL   32768
#define OFF_B    65536
#define OFF_A129 98304
#define OFF_B129 98816
#define STAGE    99328
#define SM_SIZE  (2 * STAGE)

// one k16-step of MMAs into literal acc bank ACC from stage at byte offset STGOFF
#define MMA_STEP(ACC, STGOFF, c, ks) do {                                              \
    const uint32_t _base = sb + (STGOFF);                                              \
    const uint32_t _kofs = (uint32_t)(ks) * 32;                                        \
    uint32_t _b[4][2];                                                                 \
    _Pragma("unroll")                                                                  \
    for (int p = 0; p < 2; p++) {                                                      \
        uint32_t addr = _base + OFF_B + (c) * 16384 + bBase[p] + ((_kofs + khb) ^ xorv); \
        asm volatile("ldmatrix.sync.aligned.m8n8.x4.shared.b16 {%0,%1,%2,%3}, [%4];"   \
            : "=r"(_b[2*p][0]), "=r"(_b[2*p][1]), "=r"(_b[2*p+1][0]), "=r"(_b[2*p+1][1]) \
            : "r"(addr));                                                              \
    }                                                                                  \
    uint32_t _ah[4][4], _al[4][4];                                                     \
    _Pragma("unroll")                                                                  \
    for (int mi = 0; mi < 4; mi++) {                                                   \
        uint32_t addr = _base + OFF_AH + (c) * 16384 + aBase[mi] + ((_kofs + kha) ^ xorv); \
        asm volatile("ldmatrix.sync.aligned.m8n8.x4.shared.b16 {%0,%1,%2,%3}, [%4];"   \
            : "=r"(_ah[mi][0]), "=r"(_ah[mi][1]), "=r"(_ah[mi][2]), "=r"(_ah[mi][3]) : "r"(addr)); \
    }                                                                                  \
    _Pragma("unroll")                                                                  \
    for (int mi = 0; mi < 4; mi++) {                                                   \
        uint32_t addr = _base + OFF_AL + (c) * 16384 + aBase[mi] + ((_kofs + kha) ^ xorv); \
        asm volatile("ldmatrix.sync.aligned.m8n8.x4.shared.b16 {%0,%1,%2,%3}, [%4];"   \
            : "=r"(_al[mi][0]), "=r"(_al[mi][1]), "=r"(_al[mi][2]), "=r"(_al[mi][3]) : "r"(addr)); \
    }                                                                                  \
    _Pragma("unroll")                                                                  \
    for (int mi = 0; mi < 4; mi++)                                                     \
        _Pragma("unroll")                                                              \
        for (int ni = 0; ni < 4; ni++) {                                               \
            asm volatile("mma.sync.aligned.m16n8k16.row.col.f32.f16.f16.f32 "          \
                "{%0,%1,%2,%3}, {%4,%5,%6,%7}, {%8,%9}, {%0,%1,%2,%3};"                \
                : "+f"(ACC[mi][ni][0]), "+f"(ACC[mi][ni][1]),                          \
                  "+f"(ACC[mi][ni][2]), "+f"(ACC[mi][ni][3])                           \
                : "r"(_ah[mi][0]), "r"(_ah[mi][1]), "r"(_ah[mi][2]), "r"(_ah[mi][3]),  \
                  "r"(_b[ni][0]), "r"(_b[ni][1]));                                     \
        }                                                                              \
    _Pragma("unroll")                                                                  \
    for (int mi = 0; mi < 4; mi++)                                                     \
        _Pragma("unroll")                                                              \
        for (int ni = 0; ni < 4; ni++) {                                               \
            asm volatile("mma.sync.aligned.m16n8k16.row.col.f32.f16.f16.f32 "          \
                "{%0,%1,%2,%3}, {%4,%5,%6,%7}, {%8,%9}, {%0,%1,%2,%3};"                \
                : "+f"(ACC[mi][ni][0]), "+f"(ACC[mi][ni][1]),                          \
                  "+f"(ACC[mi][ni][2]), "+f"(ACC[mi][ni][3])                           \
                : "r"(_al[mi][0]), "r"(_al[mi][1]), "r"(_al[mi][2]), "r"(_al[mi][3]),  \
                  "r"(_b[ni][0]), "r"(_b[ni][1]));                                     \
        }                                                                              \
} while (0)

// epilogue group g (literal): mi = g>>2, ni = g&3 -> 4 outputs of bank ACC
#define EPI_GROUP(ACC, SA, SBV, pm, pn, g) do {                                        \
    const int _mi = (g) >> 2, _ni = (g) & 3;                                           \
    const int _rr = mb + _mi * 16 + (L >> 2);                                          \
    const int _r0 = (pm) + _rr;                                                        \
    const int _col = (pn) + nb + _ni * 8 + (L & 3) * 2;                                \
    float _v[4];                                                                       \
    _Pragma("unroll")                                                                  \
    for (int r = 0; r < 4; r++) {                                                      \
        float _aa = (r < 2) ? SA[_mi*2] : SA[_mi*2+1];                                 \
        float _bb = SBV[_ni*2 + (r & 1)];                                              \
        float th = fmaxf(fmaf(-_aa, _bb, -ACC[_mi][_ni][r]), THMIN);                   \
        float x = fmaf(th, th, -1.0f);                                                 \
        float sq; asm("sqrt.approx.f32 %0, %1;" : "=f"(sq) : "f"(x));                  \
        float lg; asm("lg2.approx.f32 %0, %1;" : "=f"(lg) : "f"(th + sq));             \
        _v[r] = fmaxf(lg * lg * NEGLN2SQ, -50.0f);                                     \
    }                                                                                  \
    *(float2*)(out + (size_t)_r0 * NUM_ITEMS + _col)       = make_float2(_v[0], _v[1]); \
    *(float2*)(out + (size_t)(_r0 + 8) * NUM_ITEMS + _col) = make_float2(_v[2], _v[3]); \
} while (0)

#define ZERO_ACC(ACC) do {                                                             \
    _Pragma("unroll")                                                                  \
    for (int mi = 0; mi < 4; mi++)                                                     \
        _Pragma("unroll")                                                              \
        for (int ni = 0; ni < 4; ni++)                                                 \
            _Pragma("unroll")                                                          \
            for (int r = 0; r < 4; r++) ACC[mi][ni][r] = 0.0f;                         \
} while (0)

#define LOAD_SCALARS(SA, SBV, STGOFF) do {                                             \
    const uint32_t _base = sb + (STGOFF);                                              \
    _Pragma("unroll")                                                                  \
    for (int mi = 0; mi < 4; mi++) {                                                   \
        int rr = mb + mi * 16 + (L >> 2);                                              \
        asm volatile("ld.shared.f32 %0, [%1];" : "=f"(SA[mi*2])   : "r"(_base + OFF_A129 + rr * 4)); \
        asm volatile("ld.shared.f32 %0, [%1];" : "=f"(SA[mi*2+1]) : "r"(_base + OFF_A129 + (rr + 8) * 4)); \
    }                                                                                  \
    _Pragma("unroll")                                                                  \
    for (int ni = 0; ni < 4; ni++) {                                                   \
        int cc = nb + ni * 8 + (L & 3) * 2;                                            \
        asm volatile("ld.shared.f32 %0, [%1];" : "=f"(SBV[ni*2])   : "r"(_base + OFF_B129 + cc * 4)); \
        asm volatile("ld.shared.f32 %0, [%1];" : "=f"(SBV[ni*2+1]) : "r"(_base + OFF_B129 + (cc + 1) * 4)); \
    }                                                                                  \
} while (0)

__global__ __launch_bounds__(NTHREADS, 1)
void gemm_f16_persistent(float* __restrict__ out) {
    extern __shared__ __align__(1024) char smem[];
    const uint32_t sb = smem_u32(smem);
    const int tid = threadIdx.x;
    const int wid = tid >> 5;
    const int L = tid & 31;
    const int mb = (wid & 1) * 64;
    const int nb = (wid >> 1) * 32;
    const float THMIN = 1.00000011920928955f;
    const float NEGLN2SQ = -0.480453013918201f;

    const uint32_t xorv = (L & 7) * 16;
    const uint32_t kha = (L >> 4) * 16;
    const uint32_t khb = ((L >> 3) & 1) * 16;
    uint32_t aBase[4], bBase[2];
    #pragma unroll
    for (int mi = 0; mi < 4; mi++)
        aBase[mi] = (uint32_t)(mb + mi * 16 + (L & 7) + ((L >> 3) & 1) * 8) * 128;
    #pragma unroll
    for (int p = 0; p < 2; p++)
        bBase[p] = (uint32_t)(nb + p * 16 + (L & 7) + ((L >> 4) & 1) * 8) * 128;

    auto load_tile = [&](int t, uint32_t stgoff) {
        const uint32_t base = sb + stgoff;
        const int m0 = (t >> 8) * BM, n0 = (t & (NTILES_N - 1)) * BN;
        const __half* srcA = g_A16 + (size_t)m0 * 256;
        const __half* srcB = g_B16 + (size_t)n0 * 128;
        #pragma unroll
        for (int c = 0; c < 2; c++) {
            #pragma unroll
            for (int it = 0; it < 4; it++) {
                int idx = tid + it * NTHREADS; int row = idx >> 3, sg = idx & 7;
                uint32_t off = SW128((uint32_t)(row * 128 + sg * 16));
                CPA(base + OFF_AH + c * 16384 + off, srcA + row * 256 + c * 64 + sg * 8);
                CPA(base + OFF_AL + c * 16384 + off, srcA + row * 256 + 128 + c * 64 + sg * 8);
                CPA(base + OFF_B  + c * 16384 + off, srcB + row * 128 + c * 64 + sg * 8);
            }
        }
        if (tid < 32)       CPA(base + OFF_A129 + tid * 16, g_A129 + m0 + tid * 4);
        else if (tid < 64)  CPA(base + OFF_B129 + (tid - 32) * 16, g_B129 + n0 + (tid - 32) * 4);
        asm volatile("cp.async.commit_group;" ::: "memory");
    };

    float acc0[4][4][4], acc1[4][4][4];      // literal banks — never runtime-indexed
    float sA0[8], sB0[8], sA1[8], sB1[8];

    const int G = gridDim.x;
    load_tile(blockIdx.x, 0);
    int pm = 0, pn = 0;
    bool havePrev = false, lastB = false;

    for (int t = blockIdx.x; t < NTILES; t += 2 * G) {
        const int tB = t + G;
        // ---- Phase A: stage 0 -> acc0, epilogue of acc1 ----
        asm volatile("cp.async.wait_group 0;" ::: "memory");
        __syncthreads();
        if (tB < NTILES) load_tile(tB, STAGE);
        LOAD_SCALARS(sA0, sB0, 0);
        ZERO_ACC(acc0);
        #pragma unroll
        for (int s = 0; s < 8; s++) {
            MMA_STEP(acc0, 0, s >> 2, s & 3);
            if (havePrev) {
                EPI_GROUP(acc1, sA1, sB1, pm, pn, 2 * s);
                EPI_GROUP(acc1, sA1, sB1, pm, pn, 2 * s + 1);
            }
        }
        pm = (t >> 8) * BM; pn = (t & (NTILES_N - 1)) * BN;
        havePrev = true; lastB = false;
        // ---- Phase B: stage 1 -> acc1, epilogue of acc0 ----
        if (tB < NTILES) {
            asm volatile("cp.async.wait_group 0;" ::: "memory");
            __syncthreads();
            const int tC = t + 2 * G;
            if (tC < NTILES) load_tile(tC, 0);
            LOAD_SCALARS(sA1, sB1, STAGE);
            ZERO_ACC(acc1);
            #pragma unroll
            for (int s = 0; s < 8; s++) {
                MMA_STEP(acc1, STAGE, s >> 2, s & 3);
                EPI_GROUP(acc0, sA0, sB0, pm, pn, 2 * s);
                EPI_GROUP(acc0, sA0, sB0, pm, pn, 2 * s + 1);
            }
            pm = (tB >> 8) * BM; pn = (tB & (NTILES_N - 1)) * BN;
            lastB = true;
        }
    }
    // ---- tail: epilogue of the final bank (once per kernel) ----
    if (lastB) {
        #pragma unroll
        for (int g = 0; g < 16; g++) EPI_GROUP(acc1, sA1, sB1, pm, pn, g);
    } else {
        #pragma unroll
        for (int g = 0; g < 16; g++) EPI_GROUP(acc0, sA0, sB0, pm, pn, g);
    }
}

extern "C" void kernel_launch(void* const* d_in, const int* in_sizes, int n_in,
                              void* d_out, int out_size) {
    const float* h = (const float*)d_in[0];
    float* out = (float*)d_out;

    const int totPrep = (NUM_USERS + NUM_ITEMS) * 128 + NUM_USERS + NUM_ITEMS;
    prep_kernel<<<(totPrep + 255) / 256, 256>>>(h);

    int nsm = 148;
    cudaDeviceGetAttribute(&nsm, cudaDevAttrMultiProcessorCount, 0);
    cudaFuncSetAttribute(gemm_f16_persistent, cudaFuncAttributeMaxDynamicSharedMemorySize, SM_SIZE);
    gemm_f16_persistent<<<nsm, NTHREADS, SM_SIZE>>>(out);
}